// round 14
// baseline (speedup 1.0000x reference)
#include <cuda_runtime.h>
#include <cuda_fp16.h>
#include <mma.h>

using namespace nvcuda;

#define NMAX   50000
#define EMAX   800000
#define H      96
#define CIN    128
#define COUT   40
#define NLAYER 5
#define DTC    0.05f

// ---------------- device scratch (static, no allocs) ----------------
__device__ int   g_deg[NMAX];
__device__ int   g_rowptr[NMAX + 1];
__device__ int   g_cursor[NMAX];
__device__ float g_deginv[NMAX];
__device__ int   g_srcs[EMAX];            // stores src*24 (uint4 row offset)
__device__ int   g_excl[NMAX];            // per-block-local exclusive prefix
__device__ int   g_bsum[64];              // per-block degree sums
__device__ int   g_bexcl[64];             // scanned block offsets
// fp16 state ping-pong: interleaved (X,Y) half2 (row = 96 half2 = 24 uint4)
__device__ __align__(16) __half2 g_XY0[(size_t)NMAX * H];
__device__ __align__(16) __half2 g_XY1[(size_t)NMAX * H];

// ---------------- f32x2 packed-FMA helpers ----------------
__device__ __forceinline__ unsigned long long pack2(float v) {
    unsigned long long r; unsigned int u = __float_as_uint(v);
    asm("mov.b64 %0, {%1, %1};" : "=l"(r) : "r"(u));
    return r;
}
__device__ __forceinline__ unsigned long long packxy(float lo, float hi) {
    unsigned long long r;
    asm("mov.b64 %0, {%1, %2};" : "=l"(r) : "f"(lo), "f"(hi));
    return r;
}
__device__ __forceinline__ void unpack2(unsigned long long v, float& a, float& b) {
    unsigned int x, y;
    asm("mov.b64 {%0, %1}, %2;" : "=r"(x), "=r"(y) : "l"(v));
    a = __uint_as_float(x); b = __uint_as_float(y);
}
__device__ __forceinline__ void ffma2(unsigned long long& d,
                                      unsigned long long a, unsigned long long b) {
    asm("fma.rn.f32x2 %0, %1, %2, %0;" : "+l"(d) : "l"(a), "l"(b));
}

// ---------------- CSR build ----------------
__global__ void k_deg(const int* __restrict__ dst, int E) {
    int e = blockIdx.x * blockDim.x + threadIdx.x;
    if (e < E) atomicAdd(&g_deg[dst[e]], 1);
}

// stage 1: per-block (1024) scan of degrees via warp shuffles (2 barriers)
__global__ __launch_bounds__(1024) void k_scan1(int N) {
    __shared__ int wsum[32];
    int tid = threadIdx.x;
    int t = blockIdx.x * 1024 + tid;
    int d = (t < N) ? g_deg[t] : 0;
    int lane = tid & 31, wid = tid >> 5;
    int v = d;
#pragma unroll
    for (int off = 1; off < 32; off <<= 1) {
        int u = __shfl_up_sync(0xffffffffu, v, off);
        if (lane >= off) v += u;
    }
    if (lane == 31) wsum[wid] = v;
    __syncthreads();
    if (wid == 0) {
        int s = wsum[lane];
#pragma unroll
        for (int off = 1; off < 32; off <<= 1) {
            int u = __shfl_up_sync(0xffffffffu, s, off);
            if (lane >= off) s += u;
        }
        wsum[lane] = s;
    }
    __syncthreads();
    int incl = v + (wid > 0 ? wsum[wid - 1] : 0);
    if (t < N) g_excl[t] = incl - d;
    if (tid == 1023) g_bsum[blockIdx.x] = incl;
}

// stage 2: scan of block sums (<= 64 entries)
__global__ void k_scan2(int NB, int N) {
    int lane = threadIdx.x;   // 64 threads
    int s = (lane < NB) ? g_bsum[lane] : 0;
    int v = s;
#pragma unroll
    for (int off = 1; off < 64; off <<= 1) {
        int u = __shfl_up_sync(0xffffffffu, v, off);
        if ((lane & 31) >= off) v += u;
    }
    __shared__ int w0sum;
    if (lane == 31) w0sum = v;
    __syncthreads();
    int incl = v + ((lane >= 32) ? w0sum : 0);
    if (lane < NB) g_bexcl[lane] = incl - s;
    if (lane == NB - 1) g_rowptr[N] = incl;
}

// stage 3: write rowptr / cursor / deginv
__global__ __launch_bounds__(256) void k_scan3(int N) {
    int t = blockIdx.x * 256 + threadIdx.x;
    if (t < N) {
        int rp = g_bexcl[t >> 10] + g_excl[t];
        g_rowptr[t] = rp;
        g_cursor[t] = rp;
        int dg = g_deg[t];
        g_deginv[t] = 1.0f / (float)(dg > 1 ? dg : 1);
    }
}

__global__ void k_scatter(const int* __restrict__ src, const int* __restrict__ dst, int E) {
    int e = blockIdx.x * blockDim.x + threadIdx.x;
    if (e < E) {
        int p = atomicAdd(&g_cursor[dst[e]], 1);
        g_srcs[p] = src[e] * 24;    // pre-scaled uint4 row offset
    }
}

// ---------------- lift: single-pass HMMA (all 192 cols per block) ----------
// tanh(x @ [Wx,Wy]) fp16-in / fp32-acc wmma. One block = 128 rows x 192 cols
// (96 channels, B cols interleaved Wx/Wy) -> x is read ONCE. 8 warps, each
// owns 16 rows with 12 accumulator fragments. Epilogue: 6 passes of 2 frags
// through a 128x32 fp32 stage (keeps static smem at 38.75 KB).
__global__ __launch_bounds__(256) void k_lift(
        const float* __restrict__ x,
        const float* __restrict__ Wx, const float* __restrict__ bx,
        const float* __restrict__ Wy, const float* __restrict__ by,
        int N) {
    __shared__ __align__(16) __half a[128][40];      // [row][k-chunk 32]
    __shared__ __align__(16) __half b[32][200];      // [k][col 192] pad->200
    __shared__ __align__(16) float  stage[128][32];  // 2-fragment fp32 stage
    int tid = threadIdx.x;
    int wp = tid >> 5;       // warp 0..7
    int row0 = blockIdx.x * 128;

    wmma::fragment<wmma::accumulator, 16, 16, 16, float> acc[12];
#pragma unroll
    for (int c = 0; c < 12; ++c) wmma::fill_fragment(acc[c], 0.0f);

    for (int kt = 0; kt < CIN; kt += 32) {
        // a-tile: 128 rows x 32 k, fp32 -> fp16. 1024 float4 -> 4/thread.
#pragma unroll
        for (int j = 0; j < 4; ++j) {
            int f4 = tid + j * 256;
            int r = f4 >> 3;
            int kq = f4 & 7;
            float4 v = make_float4(0.f, 0.f, 0.f, 0.f);
            int gr = row0 + r;
            if (gr < N) v = *(const float4*)(x + (size_t)gr * CIN + kt + kq * 4);
            __half2 h01 = __floats2half2_rn(v.x, v.y);
            __half2 h23 = __floats2half2_rn(v.z, v.w);
            uint2 hv;
            hv.x = *(unsigned int*)&h01;
            hv.y = *(unsigned int*)&h23;
            *(uint2*)(&a[r][kq * 4]) = hv;
        }
        // b-tile: 32 k x 192 cols (interleaved Wx/Wy). 6144 halves -> 24/thread.
#pragma unroll
        for (int j = 0; j < 24; ++j) {
            int idx = tid + j * 256;
            int k = idx / 192;
            int c = idx - k * 192;
            int gk = kt + k;
            int ch = c >> 1;
            float w = (c & 1) ? Wy[gk * H + ch] : Wx[gk * H + ch];
            b[k][c] = __float2half(w);
        }
        __syncthreads();
#pragma unroll
        for (int kk = 0; kk < 32; kk += 16) {
            wmma::fragment<wmma::matrix_a, 16, 16, 16, __half, wmma::row_major> af;
            wmma::load_matrix_sync(af, &a[wp * 16][kk], 40);
#pragma unroll
            for (int c = 0; c < 12; ++c) {
                wmma::fragment<wmma::matrix_b, 16, 16, 16, __half, wmma::row_major> bf;
                wmma::load_matrix_sync(bf, &b[kk][c * 16], 200);
                wmma::mma_sync(acc[c], af, bf, acc[c]);
            }
        }
        __syncthreads();
    }
    // epilogue: 6 passes x (2 frags = 32 cols = 16 channels)
#pragma unroll
    for (int p = 0; p < 6; ++p) {
        wmma::store_matrix_sync(&stage[wp * 16][0],  acc[2 * p],     32, wmma::mem_row_major);
        wmma::store_matrix_sync(&stage[wp * 16][16], acc[2 * p + 1], 32, wmma::mem_row_major);
        __syncthreads();
        int chb = p * 16;
#pragma unroll
        for (int j = 0; j < 8; ++j) {
            int idx = tid + j * 256;     // 0..2047
            int r = idx >> 4;
            int ch = idx & 15;
            int gr = row0 + r;
            if (gr < N) {
                float2 xy = *(const float2*)&stage[r][ch * 2];
                float bxv = __ldg(bx + chb + ch);
                float byv = __ldg(by + chb + ch);
                __half2 h = __floats2half2_rn(tanhf(xy.x + bxv), tanhf(xy.y + byv));
                *(unsigned int*)(&g_XY0[(size_t)gr * H + chb + ch]) = *(unsigned int*)&h;
            }
        }
        __syncthreads();
    }
}

// ---------------- one LVConv layer (R5/R9-proven form) ----------------
__global__ __launch_bounds__(256) void k_layer(
        const uint4* __restrict__ XYin,     // rows of 24 uint4
        uint4* __restrict__ XYout,
        const float* __restrict__ al, const float* __restrict__ be,
        const float* __restrict__ ga, const float* __restrict__ de,
        int N) {
    int w = (blockIdx.x * blockDim.x + threadIdx.x) >> 5;
    int lane = threadIdx.x & 31;
    if (w >= N) return;
    bool act = lane < 24;
    int s0 = __ldg(&g_rowptr[w]);
    int s1 = __ldg(&g_rowptr[w + 1]);

    __half2 acc0 = __floats2half2_rn(0.f, 0.f);
    __half2 acc1 = acc0, acc2 = acc0, acc3 = acc0;

    int e = s0;
    for (; e + 4 <= s1; e += 4) {
        int oA = __ldg(&g_srcs[e + 0]);
        int oB = __ldg(&g_srcs[e + 1]);
        int oC = __ldg(&g_srcs[e + 2]);
        int oD = __ldg(&g_srcs[e + 3]);
        if (act) {
            uint4 vA = __ldg(XYin + oA + lane);
            uint4 vB = __ldg(XYin + oB + lane);
            uint4 vC = __ldg(XYin + oC + lane);
            uint4 vD = __ldg(XYin + oD + lane);
            acc0 = __hadd2(acc0, __hadd2(__hadd2(*(__half2*)&vA.x, *(__half2*)&vB.x),
                                         __hadd2(*(__half2*)&vC.x, *(__half2*)&vD.x)));
            acc1 = __hadd2(acc1, __hadd2(__hadd2(*(__half2*)&vA.y, *(__half2*)&vB.y),
                                         __hadd2(*(__half2*)&vC.y, *(__half2*)&vD.y)));
            acc2 = __hadd2(acc2, __hadd2(__hadd2(*(__half2*)&vA.z, *(__half2*)&vB.z),
                                         __hadd2(*(__half2*)&vC.z, *(__half2*)&vD.z)));
            acc3 = __hadd2(acc3, __hadd2(__hadd2(*(__half2*)&vA.w, *(__half2*)&vB.w),
                                         __hadd2(*(__half2*)&vC.w, *(__half2*)&vD.w)));
        }
    }
    for (; e < s1; ++e) {
        int o = __ldg(&g_srcs[e]);
        if (act) {
            uint4 v = __ldg(XYin + o + lane);
            acc0 = __hadd2(acc0, *(__half2*)&v.x);
            acc1 = __hadd2(acc1, *(__half2*)&v.y);
            acc2 = __hadd2(acc2, *(__half2*)&v.z);
            acc3 = __hadd2(acc3, *(__half2*)&v.w);
        }
    }
    if (!act) return;

    float dinv = __ldg(&g_deginv[w]);
    float2 a0 = __half22float2(acc0);
    float2 a1 = __half22float2(acc1);
    float2 a2 = __half22float2(acc2);
    float2 a3 = __half22float2(acc3);
    float aggX[4] = {a0.x * dinv, a1.x * dinv, a2.x * dinv, a3.x * dinv};
    float aggY[4] = {a0.y * dinv, a1.y * dinv, a2.y * dinv, a3.y * dinv};

    int c0 = lane * 4;
    size_t rbase = (size_t)w * 24 + lane;
    uint4 sv = __ldg(XYin + rbase);
    float2 s0f = __half22float2(*(__half2*)&sv.x);
    float2 s1f = __half22float2(*(__half2*)&sv.y);
    float2 s2f = __half22float2(*(__half2*)&sv.z);
    float2 s3f = __half22float2(*(__half2*)&sv.w);

    float4 alv = *(const float4*)(al + c0);
    float4 bev = *(const float4*)(be + c0);
    float4 gav = *(const float4*)(ga + c0);
    float4 dev = *(const float4*)(de + c0);

    float Xn0 = s0f.x + DTC * s0f.x * (alv.x - bev.x * aggY[0]);
    float Yn0 = s0f.y + DTC * s0f.y * (-gav.x + dev.x * aggX[0]);
    float Xn1 = s1f.x + DTC * s1f.x * (alv.y - bev.y * aggY[1]);
    float Yn1 = s1f.y + DTC * s1f.y * (-gav.y + dev.y * aggX[1]);
    float Xn2 = s2f.x + DTC * s2f.x * (alv.z - bev.z * aggY[2]);
    float Yn2 = s2f.y + DTC * s2f.y * (-gav.z + dev.z * aggX[2]);
    float Xn3 = s3f.x + DTC * s3f.x * (alv.w - bev.w * aggY[3]);
    float Yn3 = s3f.y + DTC * s3f.y * (-gav.w + dev.w * aggX[3]);

    __half2 h0 = __floats2half2_rn(Xn0, Yn0);
    __half2 h1 = __floats2half2_rn(Xn1, Yn1);
    __half2 h2 = __floats2half2_rn(Xn2, Yn2);
    __half2 h3 = __floats2half2_rn(Xn3, Yn3);
    uint4 hv;
    hv.x = *(unsigned int*)&h0; hv.y = *(unsigned int*)&h1;
    hv.z = *(unsigned int*)&h2; hv.w = *(unsigned int*)&h3;
    XYout[rbase] = hv;
}

// ---------------- readout: out = [X|Y] @ Wr + br, fp16 state, f32x2 math ----
__global__ __launch_bounds__(128) void k_readout(
        const uint4* __restrict__ XY,
        const float* __restrict__ Wr, const float* __restrict__ br,
        float* __restrict__ out, int N) {
    __shared__ float2 xs2[128][33];
    __shared__ float  wsX[32][COUT];
    __shared__ float  wsY[32][COUT];
    int tid = threadIdx.x;
    int tx = tid & 7;
    int ty = tid >> 3;
    int row0 = blockIdx.x * 128;
    unsigned long long acc2[4][5];
#pragma unroll
    for (int p = 0; p < 4; ++p)
#pragma unroll
        for (int j = 0; j < 5; ++j) acc2[p][j] = 0ull;

    for (int kt = 0; kt < H; kt += 32) {
#pragma unroll
        for (int j = 0; j < 8; ++j) {
            int u4 = tid + j * 128;
            int r = u4 >> 3;
            int q = u4 & 7;
            int gr = row0 + r;
            uint4 v = make_uint4(0u, 0u, 0u, 0u);
            if (gr < N) v = __ldg(XY + (size_t)gr * 24 + (kt >> 2) + q);
            int cc = q * 4;
            xs2[r][cc + 0] = __half22float2(*(__half2*)&v.x);
            xs2[r][cc + 1] = __half22float2(*(__half2*)&v.y);
            xs2[r][cc + 2] = __half22float2(*(__half2*)&v.z);
            xs2[r][cc + 3] = __half22float2(*(__half2*)&v.w);
        }
#pragma unroll
        for (int j = 0; j < 10; ++j) {
            int idx = tid + j * 128;
            if (idx < 32 * COUT) {
                int k = idx / COUT;
                int c = idx - k * COUT;
                wsX[k][c] = Wr[(size_t)(kt + k) * COUT + c];
                wsY[k][c] = Wr[(size_t)(H + kt + k) * COUT + c];
            }
        }
        __syncthreads();
#pragma unroll
        for (int k = 0; k < 32; ++k) {
            float2 xv[8];
#pragma unroll
            for (int i = 0; i < 8; ++i) xv[i] = xs2[ty * 8 + i][k];
            unsigned long long XA[4], YA[4];
#pragma unroll
            for (int p = 0; p < 4; ++p) {
                XA[p] = packxy(xv[2 * p].x, xv[2 * p + 1].x);
                YA[p] = packxy(xv[2 * p].y, xv[2 * p + 1].y);
            }
#pragma unroll
            for (int j = 0; j < 5; ++j) {
                unsigned long long wxj = pack2(wsX[k][tx * 5 + j]);
                unsigned long long wyj = pack2(wsY[k][tx * 5 + j]);
#pragma unroll
                for (int p = 0; p < 4; ++p) {
                    ffma2(acc2[p][j], XA[p], wxj);
                    ffma2(acc2[p][j], YA[p], wyj);
                }
            }
        }
        __syncthreads();
    }
#pragma unroll
    for (int p = 0; p < 4; ++p) {
        int gr0 = row0 + ty * 8 + 2 * p;
#pragma unroll
        for (int j = 0; j < 5; ++j) {
            float vlo, vhi;
            unpack2(acc2[p][j], vlo, vhi);
            float bb = br[tx * 5 + j];
            if (gr0 < N)     out[(size_t)gr0 * COUT + tx * 5 + j] = vlo + bb;
            if (gr0 + 1 < N) out[(size_t)(gr0 + 1) * COUT + tx * 5 + j] = vhi + bb;
        }
    }
}

// ---------------- launch ----------------
extern "C" void kernel_launch(void* const* d_in, const int* in_sizes, int n_in,
                              void* d_out, int out_size) {
    const float* x  = (const float*)d_in[0];
    const int*   ei = (const int*)d_in[1];
    const float* Wx = (const float*)d_in[2];
    const float* bx = (const float*)d_in[3];
    const float* Wy = (const float*)d_in[4];
    const float* by = (const float*)d_in[5];
    const float* al = (const float*)d_in[6];
    const float* be = (const float*)d_in[7];
    const float* ga = (const float*)d_in[8];
    const float* de = (const float*)d_in[9];
    const float* Wr = (const float*)d_in[10];
    const float* br = (const float*)d_in[11];
    float* out = (float*)d_out;

    int N = in_sizes[0] / CIN;
    int E = in_sizes[1] / 2;
    if (N > NMAX) N = NMAX;
    if (E > EMAX) E = EMAX;
    const int* srcp = ei;
    const int* dstp = ei + E;

    // one-time side stream + fork/join events (no device memory involved)
    static cudaStream_t s2 = nullptr;
    static cudaEvent_t evF = nullptr, evJ = nullptr;
    if (s2 == nullptr) {
        cudaStreamCreateWithFlags(&s2, cudaStreamNonBlocking);
        cudaEventCreateWithFlags(&evF, cudaEventDisableTiming);
        cudaEventCreateWithFlags(&evJ, cudaEventDisableTiming);
    }

    void* degp;
    cudaGetSymbolAddress(&degp, g_deg);

    int NB = (N + 1023) >> 10;

    // fork: CSR chain on s2, lift on main stream (independent until layers)
    cudaEventRecord(evF, 0);
    cudaStreamWaitEvent(s2, evF, 0);

    cudaMemsetAsync(degp, 0, (size_t)N * sizeof(int), s2);
    k_deg<<<(E + 255) / 256, 256, 0, s2>>>(dstp, E);
    k_scan1<<<NB, 1024, 0, s2>>>(N);
    k_scan2<<<1, 64, 0, s2>>>(NB, N);
    k_scan3<<<(N + 255) / 256, 256, 0, s2>>>(N);
    k_scatter<<<(E + 255) / 256, 256, 0, s2>>>(srcp, dstp, E);
    cudaEventRecord(evJ, s2);

    k_lift<<<(N + 127) / 128, 256>>>(x, Wx, bx, Wy, by, N);

    // join: layers need both CSR and lifted state
    cudaStreamWaitEvent(0, evJ, 0);

    uint4* XYb[2];
    cudaGetSymbolAddress((void**)&XYb[0], g_XY0);
    cudaGetSymbolAddress((void**)&XYb[1], g_XY1);

    int layerBlocks = (N * 32 + 255) / 256;
    for (int l = 0; l < NLAYER; ++l) {
        k_layer<<<layerBlocks, 256>>>(XYb[l & 1], XYb[(l + 1) & 1],
                                      al + l * H, be + l * H, ga + l * H, de + l * H, N);
    }
    k_readout<<<(N + 127) / 128, 128>>>(XYb[NLAYER & 1], Wr, br, out, N);
}

// round 15
// speedup vs baseline: 1.0273x; 1.0273x over previous
#include <cuda_runtime.h>
#include <cuda_fp16.h>
#include <mma.h>

using namespace nvcuda;

#define NMAX   50000
#define EMAX   800000
#define H      96
#define CIN    128
#define COUT   40
#define NLAYER 5
#define DTC    0.05f

// ---------------- device scratch (static, no allocs) ----------------
__device__ int   g_deg[NMAX];
__device__ int   g_rowptr[NMAX + 1];
__device__ int   g_cursor[NMAX];
__device__ float g_deginv[NMAX];
__device__ int   g_srcs[EMAX];            // stores src*24 (uint4 row offset)
__device__ int   g_excl[NMAX];            // per-block-local exclusive prefix
__device__ int   g_bsum[64];              // per-block degree sums
__device__ int   g_bexcl[64];             // scanned block offsets
// fp16 state ping-pong: interleaved (X,Y) half2 (row = 96 half2 = 24 uint4)
__device__ __align__(16) __half2 g_XY0[(size_t)NMAX * H];
__device__ __align__(16) __half2 g_XY1[(size_t)NMAX * H];
// fp16 copies of GEMM operands (built once per launch)
__device__ __align__(16) __half g_x16[(size_t)NMAX * CIN];
__device__ __align__(16) __half g_B16[CIN * 192];   // interleaved (Wx,Wy) cols

// ---------------- f32x2 packed-FMA helpers ----------------
__device__ __forceinline__ unsigned long long pack2(float v) {
    unsigned long long r; unsigned int u = __float_as_uint(v);
    asm("mov.b64 %0, {%1, %1};" : "=l"(r) : "r"(u));
    return r;
}
__device__ __forceinline__ unsigned long long packxy(float lo, float hi) {
    unsigned long long r;
    asm("mov.b64 %0, {%1, %2};" : "=l"(r) : "f"(lo), "f"(hi));
    return r;
}
__device__ __forceinline__ void unpack2(unsigned long long v, float& a, float& b) {
    unsigned int x, y;
    asm("mov.b64 {%0, %1}, %2;" : "=r"(x), "=r"(y) : "l"(v));
    a = __uint_as_float(x); b = __uint_as_float(y);
}
__device__ __forceinline__ void ffma2(unsigned long long& d,
                                      unsigned long long a, unsigned long long b) {
    asm("fma.rn.f32x2 %0, %1, %2, %0;" : "+l"(d) : "l"(a), "l"(b));
}

// ---------------- CSR build ----------------
__global__ void k_deg(const int* __restrict__ dst, int E) {
    int e = blockIdx.x * blockDim.x + threadIdx.x;
    if (e < E) atomicAdd(&g_deg[dst[e]], 1);
}

__global__ __launch_bounds__(1024) void k_scan1(int N) {
    __shared__ int wsum[32];
    int tid = threadIdx.x;
    int t = blockIdx.x * 1024 + tid;
    int d = (t < N) ? g_deg[t] : 0;
    int lane = tid & 31, wid = tid >> 5;
    int v = d;
#pragma unroll
    for (int off = 1; off < 32; off <<= 1) {
        int u = __shfl_up_sync(0xffffffffu, v, off);
        if (lane >= off) v += u;
    }
    if (lane == 31) wsum[wid] = v;
    __syncthreads();
    if (wid == 0) {
        int s = wsum[lane];
#pragma unroll
        for (int off = 1; off < 32; off <<= 1) {
            int u = __shfl_up_sync(0xffffffffu, s, off);
            if (lane >= off) s += u;
        }
        wsum[lane] = s;
    }
    __syncthreads();
    int incl = v + (wid > 0 ? wsum[wid - 1] : 0);
    if (t < N) g_excl[t] = incl - d;
    if (tid == 1023) g_bsum[blockIdx.x] = incl;
}

__global__ void k_scan2(int NB, int N) {
    int lane = threadIdx.x;   // 64 threads
    int s = (lane < NB) ? g_bsum[lane] : 0;
    int v = s;
#pragma unroll
    for (int off = 1; off < 64; off <<= 1) {
        int u = __shfl_up_sync(0xffffffffu, v, off);
        if ((lane & 31) >= off) v += u;
    }
    __shared__ int w0sum;
    if (lane == 31) w0sum = v;
    __syncthreads();
    int incl = v + ((lane >= 32) ? w0sum : 0);
    if (lane < NB) g_bexcl[lane] = incl - s;
    if (lane == NB - 1) g_rowptr[N] = incl;
}

__global__ __launch_bounds__(256) void k_scan3(int N) {
    int t = blockIdx.x * 256 + threadIdx.x;
    if (t < N) {
        int rp = g_bexcl[t >> 10] + g_excl[t];
        g_rowptr[t] = rp;
        g_cursor[t] = rp;
        int dg = g_deg[t];
        g_deginv[t] = 1.0f / (float)(dg > 1 ? dg : 1);
    }
}

__global__ void k_scatter(const int* __restrict__ src, const int* __restrict__ dst, int E) {
    int e = blockIdx.x * blockDim.x + threadIdx.x;
    if (e < E) {
        int p = atomicAdd(&g_cursor[dst[e]], 1);
        g_srcs[p] = src[e] * 24;    // pre-scaled uint4 row offset
    }
}

// ---------------- operand pre-conversion ----------------
// x -> fp16, vectorized 8 elements/thread
__global__ __launch_bounds__(256) void k_x16(const float* __restrict__ x, int total8) {
    int i = blockIdx.x * 256 + threadIdx.x;
    if (i < total8) {
        const float4* p = (const float4*)x + (size_t)i * 2;
        float4 v0 = p[0], v1 = p[1];
        __half2 h0 = __floats2half2_rn(v0.x, v0.y);
        __half2 h1 = __floats2half2_rn(v0.z, v0.w);
        __half2 h2 = __floats2half2_rn(v1.x, v1.y);
        __half2 h3 = __floats2half2_rn(v1.z, v1.w);
        uint4 o;
        o.x = *(unsigned int*)&h0; o.y = *(unsigned int*)&h1;
        o.z = *(unsigned int*)&h2; o.w = *(unsigned int*)&h3;
        ((uint4*)g_x16)[i] = o;
    }
}

// interleaved fp16 B: col 2p = Wx[:,p], col 2p+1 = Wy[:,p]
__global__ __launch_bounds__(256) void k_b16(const float* __restrict__ Wx,
                                             const float* __restrict__ Wy) {
    int idx = blockIdx.x * 256 + threadIdx.x;
    if (idx < CIN * 192) {
        int k = idx / 192;
        int c = idx - k * 192;
        int ch = c >> 1;
        float w = (c & 1) ? Wy[k * H + ch] : Wx[k * H + ch];
        g_B16[idx] = __float2half(w);
    }
}

// ---------------- lift: HMMA with prebuilt fp16 operands ----------------
// R13 geometry (128 rows x 64 cols per block, gridDim.y=3, 8 warps, 4 frags)
// but all tile fills are pure vector LDG.128 -> STS.128 (no CVT, no selects).
__global__ __launch_bounds__(256) void k_lift(
        const float* __restrict__ bx, const float* __restrict__ by, int N) {
    __shared__ __align__(16) __half a[128][40];     // [row][k-chunk 32]
    __shared__ __align__(16) __half b[32][72];      // [k][col 64]
    __shared__ __align__(16) float  stage[128][64];
    int tid = threadIdx.x;
    int wp = tid >> 5;
    int cb = blockIdx.y;     // 0..2 (32 channels = 64 interleaved cols)
    int c0 = cb * 32;
    int row0 = blockIdx.x * 128;

    wmma::fragment<wmma::accumulator, 16, 16, 16, float> acc[4];
#pragma unroll
    for (int c = 0; c < 4; ++c) wmma::fill_fragment(acc[c], 0.0f);

    for (int kt = 0; kt < CIN; kt += 32) {
        // a-tile: 128 rows x 32 k halves = 512 uint4 -> 2/thread
#pragma unroll
        for (int j = 0; j < 2; ++j) {
            int i4 = tid + j * 256;
            int r = i4 >> 2;
            int q = i4 & 3;
            uint4 v = make_uint4(0u, 0u, 0u, 0u);
            int gr = row0 + r;
            if (gr < N) v = *(const uint4*)(g_x16 + (size_t)gr * CIN + kt + q * 8);
            *(uint4*)&a[r][q * 8] = v;
        }
        // b-tile: 32 k x 64 cols halves = 256 uint4 -> 1/thread
        {
            int k = tid >> 3;
            int q = tid & 7;
            uint4 v = *(const uint4*)(g_B16 + (size_t)(kt + k) * 192 + cb * 64 + q * 8);
            *(uint4*)&b[k][q * 8] = v;
        }
        __syncthreads();
#pragma unroll
        for (int kk = 0; kk < 32; kk += 16) {
            wmma::fragment<wmma::matrix_a, 16, 16, 16, __half, wmma::row_major> af;
            wmma::load_matrix_sync(af, &a[wp * 16][kk], 40);
#pragma unroll
            for (int c = 0; c < 4; ++c) {
                wmma::fragment<wmma::matrix_b, 16, 16, 16, __half, wmma::row_major> bf;
                wmma::load_matrix_sync(bf, &b[kk][c * 16], 72);
                wmma::mma_sync(acc[c], af, bf, acc[c]);
            }
        }
        __syncthreads();
    }
#pragma unroll
    for (int c = 0; c < 4; ++c)
        wmma::store_matrix_sync(&stage[wp * 16][c * 16], acc[c], 64, wmma::mem_row_major);
    __syncthreads();
#pragma unroll
    for (int j = 0; j < 16; ++j) {
        int idx = tid + j * 256;       // 0..4095
        int r = idx >> 5;
        int p = idx & 31;
        int gr = row0 + r;
        if (gr < N) {
            float2 xy = *(const float2*)&stage[r][p * 2];
            float bxv = __ldg(bx + c0 + p);
            float byv = __ldg(by + c0 + p);
            __half2 h = __floats2half2_rn(tanhf(xy.x + bxv), tanhf(xy.y + byv));
            *(unsigned int*)(&g_XY0[(size_t)gr * H + c0 + p]) = *(unsigned int*)&h;
        }
    }
}

// ---------------- one LVConv layer (R5/R9-proven form) ----------------
__global__ __launch_bounds__(256) void k_layer(
        const uint4* __restrict__ XYin,     // rows of 24 uint4
        uint4* __restrict__ XYout,
        const float* __restrict__ al, const float* __restrict__ be,
        const float* __restrict__ ga, const float* __restrict__ de,
        int N) {
    int w = (blockIdx.x * blockDim.x + threadIdx.x) >> 5;
    int lane = threadIdx.x & 31;
    if (w >= N) return;
    bool act = lane < 24;
    int s0 = __ldg(&g_rowptr[w]);
    int s1 = __ldg(&g_rowptr[w + 1]);

    __half2 acc0 = __floats2half2_rn(0.f, 0.f);
    __half2 acc1 = acc0, acc2 = acc0, acc3 = acc0;

    int e = s0;
    for (; e + 4 <= s1; e += 4) {
        int oA = __ldg(&g_srcs[e + 0]);
        int oB = __ldg(&g_srcs[e + 1]);
        int oC = __ldg(&g_srcs[e + 2]);
        int oD = __ldg(&g_srcs[e + 3]);
        if (act) {
            uint4 vA = __ldg(XYin + oA + lane);
            uint4 vB = __ldg(XYin + oB + lane);
            uint4 vC = __ldg(XYin + oC + lane);
            uint4 vD = __ldg(XYin + oD + lane);
            acc0 = __hadd2(acc0, __hadd2(__hadd2(*(__half2*)&vA.x, *(__half2*)&vB.x),
                                         __hadd2(*(__half2*)&vC.x, *(__half2*)&vD.x)));
            acc1 = __hadd2(acc1, __hadd2(__hadd2(*(__half2*)&vA.y, *(__half2*)&vB.y),
                                         __hadd2(*(__half2*)&vC.y, *(__half2*)&vD.y)));
            acc2 = __hadd2(acc2, __hadd2(__hadd2(*(__half2*)&vA.z, *(__half2*)&vB.z),
                                         __hadd2(*(__half2*)&vC.z, *(__half2*)&vD.z)));
            acc3 = __hadd2(acc3, __hadd2(__hadd2(*(__half2*)&vA.w, *(__half2*)&vB.w),
                                         __hadd2(*(__half2*)&vC.w, *(__half2*)&vD.w)));
        }
    }
    for (; e < s1; ++e) {
        int o = __ldg(&g_srcs[e]);
        if (act) {
            uint4 v = __ldg(XYin + o + lane);
            acc0 = __hadd2(acc0, *(__half2*)&v.x);
            acc1 = __hadd2(acc1, *(__half2*)&v.y);
            acc2 = __hadd2(acc2, *(__half2*)&v.z);
            acc3 = __hadd2(acc3, *(__half2*)&v.w);
        }
    }
    if (!act) return;

    float dinv = __ldg(&g_deginv[w]);
    float2 a0 = __half22float2(acc0);
    float2 a1 = __half22float2(acc1);
    float2 a2 = __half22float2(acc2);
    float2 a3 = __half22float2(acc3);
    float aggX[4] = {a0.x * dinv, a1.x * dinv, a2.x * dinv, a3.x * dinv};
    float aggY[4] = {a0.y * dinv, a1.y * dinv, a2.y * dinv, a3.y * dinv};

    int c0 = lane * 4;
    size_t rbase = (size_t)w * 24 + lane;
    uint4 sv = __ldg(XYin + rbase);
    float2 s0f = __half22float2(*(__half2*)&sv.x);
    float2 s1f = __half22float2(*(__half2*)&sv.y);
    float2 s2f = __half22float2(*(__half2*)&sv.z);
    float2 s3f = __half22float2(*(__half2*)&sv.w);

    float4 alv = *(const float4*)(al + c0);
    float4 bev = *(const float4*)(be + c0);
    float4 gav = *(const float4*)(ga + c0);
    float4 dev = *(const float4*)(de + c0);

    float Xn0 = s0f.x + DTC * s0f.x * (alv.x - bev.x * aggY[0]);
    float Yn0 = s0f.y + DTC * s0f.y * (-gav.x + dev.x * aggX[0]);
    float Xn1 = s1f.x + DTC * s1f.x * (alv.y - bev.y * aggY[1]);
    float Yn1 = s1f.y + DTC * s1f.y * (-gav.y + dev.y * aggX[1]);
    float Xn2 = s2f.x + DTC * s2f.x * (alv.z - bev.z * aggY[2]);
    float Yn2 = s2f.y + DTC * s2f.y * (-gav.z + dev.z * aggX[2]);
    float Xn3 = s3f.x + DTC * s3f.x * (alv.w - bev.w * aggY[3]);
    float Yn3 = s3f.y + DTC * s3f.y * (-gav.w + dev.w * aggX[3]);

    __half2 h0 = __floats2half2_rn(Xn0, Yn0);
    __half2 h1 = __floats2half2_rn(Xn1, Yn1);
    __half2 h2 = __floats2half2_rn(Xn2, Yn2);
    __half2 h3 = __floats2half2_rn(Xn3, Yn3);
    uint4 hv;
    hv.x = *(unsigned int*)&h0; hv.y = *(unsigned int*)&h1;
    hv.z = *(unsigned int*)&h2; hv.w = *(unsigned int*)&h3;
    XYout[rbase] = hv;
}

// ---------------- readout: out = [X|Y] @ Wr + br, fp16 state, f32x2 math ----
__global__ __launch_bounds__(128) void k_readout(
        const uint4* __restrict__ XY,
        const float* __restrict__ Wr, const float* __restrict__ br,
        float* __restrict__ out, int N) {
    __shared__ float2 xs2[128][33];
    __shared__ float  wsX[32][COUT];
    __shared__ float  wsY[32][COUT];
    int tid = threadIdx.x;
    int tx = tid & 7;
    int ty = tid >> 3;
    int row0 = blockIdx.x * 128;
    unsigned long long acc2[4][5];
#pragma unroll
    for (int p = 0; p < 4; ++p)
#pragma unroll
        for (int j = 0; j < 5; ++j) acc2[p][j] = 0ull;

    for (int kt = 0; kt < H; kt += 32) {
#pragma unroll
        for (int j = 0; j < 8; ++j) {
            int u4 = tid + j * 128;
            int r = u4 >> 3;
            int q = u4 & 7;
            int gr = row0 + r;
            uint4 v = make_uint4(0u, 0u, 0u, 0u);
            if (gr < N) v = __ldg(XY + (size_t)gr * 24 + (kt >> 2) + q);
            int cc = q * 4;
            xs2[r][cc + 0] = __half22float2(*(__half2*)&v.x);
            xs2[r][cc + 1] = __half22float2(*(__half2*)&v.y);
            xs2[r][cc + 2] = __half22float2(*(__half2*)&v.z);
            xs2[r][cc + 3] = __half22float2(*(__half2*)&v.w);
        }
#pragma unroll
        for (int j = 0; j < 10; ++j) {
            int idx = tid + j * 128;
            if (idx < 32 * COUT) {
                int k = idx / COUT;
                int c = idx - k * COUT;
                wsX[k][c] = Wr[(size_t)(kt + k) * COUT + c];
                wsY[k][c] = Wr[(size_t)(H + kt + k) * COUT + c];
            }
        }
        __syncthreads();
#pragma unroll
        for (int k = 0; k < 32; ++k) {
            float2 xv[8];
#pragma unroll
            for (int i = 0; i < 8; ++i) xv[i] = xs2[ty * 8 + i][k];
            unsigned long long XA[4], YA[4];
#pragma unroll
            for (int p = 0; p < 4; ++p) {
                XA[p] = packxy(xv[2 * p].x, xv[2 * p + 1].x);
                YA[p] = packxy(xv[2 * p].y, xv[2 * p + 1].y);
            }
#pragma unroll
            for (int j = 0; j < 5; ++j) {
                unsigned long long wxj = pack2(wsX[k][tx * 5 + j]);
                unsigned long long wyj = pack2(wsY[k][tx * 5 + j]);
#pragma unroll
                for (int p = 0; p < 4; ++p) {
                    ffma2(acc2[p][j], XA[p], wxj);
                    ffma2(acc2[p][j], YA[p], wyj);
                }
            }
        }
        __syncthreads();
    }
#pragma unroll
    for (int p = 0; p < 4; ++p) {
        int gr0 = row0 + ty * 8 + 2 * p;
#pragma unroll
        for (int j = 0; j < 5; ++j) {
            float vlo, vhi;
            unpack2(acc2[p][j], vlo, vhi);
            float bb = br[tx * 5 + j];
            if (gr0 < N)     out[(size_t)gr0 * COUT + tx * 5 + j] = vlo + bb;
            if (gr0 + 1 < N) out[(size_t)(gr0 + 1) * COUT + tx * 5 + j] = vhi + bb;
        }
    }
}

// ---------------- launch ----------------
extern "C" void kernel_launch(void* const* d_in, const int* in_sizes, int n_in,
                              void* d_out, int out_size) {
    const float* x  = (const float*)d_in[0];
    const int*   ei = (const int*)d_in[1];
    const float* Wx = (const float*)d_in[2];
    const float* bx = (const float*)d_in[3];
    const float* Wy = (const float*)d_in[4];
    const float* by = (const float*)d_in[5];
    const float* al = (const float*)d_in[6];
    const float* be = (const float*)d_in[7];
    const float* ga = (const float*)d_in[8];
    const float* de = (const float*)d_in[9];
    const float* Wr = (const float*)d_in[10];
    const float* br = (const float*)d_in[11];
    float* out = (float*)d_out;

    int N = in_sizes[0] / CIN;
    int E = in_sizes[1] / 2;
    if (N > NMAX) N = NMAX;
    if (E > EMAX) E = EMAX;
    const int* srcp = ei;
    const int* dstp = ei + E;

    // one-time side stream + fork/join events (no device memory involved)
    static cudaStream_t s2 = nullptr;
    static cudaEvent_t evF = nullptr, evB = nullptr, evJ = nullptr;
    if (s2 == nullptr) {
        cudaStreamCreateWithFlags(&s2, cudaStreamNonBlocking);
        cudaEventCreateWithFlags(&evF, cudaEventDisableTiming);
        cudaEventCreateWithFlags(&evB, cudaEventDisableTiming);
        cudaEventCreateWithFlags(&evJ, cudaEventDisableTiming);
    }

    void* degp;
    cudaGetSymbolAddress(&degp, g_deg);

    int NB = (N + 1023) >> 10;

    // fork: B16 build + CSR chain on s2; x16 + lift on main stream
    cudaEventRecord(evF, 0);
    cudaStreamWaitEvent(s2, evF, 0);

    k_b16<<<(CIN * 192 + 255) / 256, 256, 0, s2>>>(Wx, Wy);
    cudaEventRecord(evB, s2);

    cudaMemsetAsync(degp, 0, (size_t)N * sizeof(int), s2);
    k_deg<<<(E + 255) / 256, 256, 0, s2>>>(dstp, E);
    k_scan1<<<NB, 1024, 0, s2>>>(N);
    k_scan2<<<1, 64, 0, s2>>>(NB, N);
    k_scan3<<<(N + 255) / 256, 256, 0, s2>>>(N);
    k_scatter<<<(E + 255) / 256, 256, 0, s2>>>(srcp, dstp, E);
    cudaEventRecord(evJ, s2);

    k_x16<<<(N * 16 + 255) / 256, 256>>>(x, N * 16);
    cudaStreamWaitEvent(0, evB, 0);

    dim3 gl((N + 127) / 128, 3);
    k_lift<<<gl, 256>>>(bx, by, N);

    // join: layers need both CSR and lifted state
    cudaStreamWaitEvent(0, evJ, 0);

    uint4* XYb[2];
    cudaGetSymbolAddress((void**)&XYb[0], g_XY0);
    cudaGetSymbolAddress((void**)&XYb[1], g_XY1);

    int layerBlocks = (N * 32 + 255) / 256;
    for (int l = 0; l < NLAYER; ++l) {
        k_layer<<<layerBlocks, 256>>>(XYb[l & 1], XYb[(l + 1) & 1],
                                      al + l * H, be + l * H, ga + l * H, de + l * H, N);
    }
    k_readout<<<(N + 127) / 128, 128>>>(XYb[NLAYER & 1], Wr, br, out, N);
}